// round 11
// baseline (speedup 1.0000x reference)
#include <cuda_runtime.h>
#include <cuda_bf16.h>
#include <math.h>

// ---------------------------------------------------------------------------
// Problem constants
//   x [64,2500,1] -> initGCN -> [64,2500,64]
//   block(k=50) -> [64,625,64]; block(k=25) -> [64,144,64]; block(k=12) -> [64,36,64]
//   flatten [64,2304] -> SN-linear(256) -> celu -> SN-linear(256) -> celu
// ---------------------------------------------------------------------------

#define NB 64     // batch
#define NC 64     // channels

// scratch (static __device__ arrays; no allocation allowed)
__device__ float g_A [64*2500*64];   // init output / block inputs
__device__ float g_X1[64*2500*64];   // x1 of current block
__device__ float g_P1[64*625*64];    // stage1 pooled
__device__ float g_P2[64*144*64];    // stage2 pooled
__device__ float g_F [64*36*64];     // stage3 pooled = flattened features
__device__ float g_G1[256*256];
__device__ float g_G2[256*256];
__device__ float g_Sig[2];
__device__ float g_H1[64*256];

__device__ __forceinline__ float rdeg(int i, int j, int k) {
    int ci = 1 + (i > 0) + (i < k - 1);
    int cj = 1 + (j > 0) + (j < k - 1);
    return rsqrtf((float)(ci * cj));
}

// ---------------------------------------------------------------------------
// init GCN: h = aggregate(x * w_init) + b_init.  Since Cin=1:
//   s[b,n] = r(n) * sum_nbr r(nbr) * x[b,nbr];  out[b,n,c] = s * w0[c] + b0[c]
// ---------------------------------------------------------------------------
__global__ void k_init(const float* __restrict__ x, const float* __restrict__ w0,
                       const float* __restrict__ b0, float* __restrict__ out) {
    __shared__ float ws[64], bs[64];
    if (threadIdx.x < 64)      ws[threadIdx.x]      = w0[threadIdx.x];
    else if (threadIdx.x < 128) bs[threadIdx.x-64]  = b0[threadIdx.x-64];
    __syncthreads();
    int idx = blockIdx.x * 256 + threadIdx.x;
    if (idx >= NB * 2500) return;
    int b = idx / 2500, n = idx - b * 2500;
    int i = n / 50, j = n - i * 50;
    float s = 0.f;
#pragma unroll
    for (int di = -1; di <= 1; di++)
#pragma unroll
        for (int dj = -1; dj <= 1; dj++) {
            int ii = i + di, jj = j + dj;
            if (ii >= 0 && ii < 50 && jj >= 0 && jj < 50)
                s += rdeg(ii, jj, 50) * x[b * 2500 + ii * 50 + jj];
        }
    s *= rdeg(i, j, 50);
    float4* op = (float4*)(out + (size_t)idx * 64);
#pragma unroll
    for (int q = 0; q < 16; q++) {
        float4 w = ((float4*)ws)[q], bb = ((float4*)bs)[q];
        op[q] = make_float4(fmaf(s, w.x, bb.x), fmaf(s, w.y, bb.y),
                            fmaf(s, w.z, bb.z), fmaf(s, w.w, bb.w));
    }
}

// ---------------------------------------------------------------------------
// Fused GCN layer: per-CTA spatial tile (TI x TJ) + halo.
//  1) load X halo into smem (OOB -> 0)
//  2) Hs[node] = r(node) * (Xs[node] @ W)
//  3) per interior node (one warp): 3x3 stencil sum * r(dst) + bias,
//     InstanceNorm over C=64, (+residual), CELU
//  4) POOL: 2x2 max via smem staging, write pooled tensor
// Grid: (tilesX, tilesY, B).  blockDim = 256.
// ---------------------------------------------------------------------------
template<int K, int TI, int TJ, bool POOL, bool RES>
__global__ void k_gcn(const float* __restrict__ in,      // [B,K*K,64]
                      const float* __restrict__ resid,   // [B,K*K,64] (RES)
                      const float* __restrict__ W,       // [64,64] (in,out)
                      const float* __restrict__ bias,    // [64]
                      float* __restrict__ out) {
    constexpr int HW = TJ + 2;
    constexpr int HN = (TI + 2) * (TJ + 2);
    constexpr int REG = POOL ? (K / 2) * 2 : K;

    extern __shared__ float sm[];
    float* Ws = sm;                  // 4096
    float* Bs = Ws + 4096;           // 64
    float* Xs = Bs + 64;             // HN*64
    float* Hs = Xs + HN * 64;        // HN*64
    float* Ys = Hs + HN * 64;        // TI*TJ*64 (POOL only)

    const int tid = threadIdx.x;
    const int b = blockIdx.z;
    const int ti0 = blockIdx.y * TI;
    const int tj0 = blockIdx.x * TJ;
    const size_t inB = (size_t)b * K * K * 64;

    // load W + bias
    for (int q = tid; q < 1024; q += 256)
        ((float4*)Ws)[q] = ((const float4*)W)[q];
    if (tid < 16) ((float4*)Bs)[tid] = ((const float4*)bias)[tid];

    // load halo X (zero outside the K x K grid)
    for (int q = tid; q < HN * 16; q += 256) {
        int node = q >> 4, part = q & 15;
        int hi = node / HW, hj = node - hi * HW;
        int gi = ti0 - 1 + hi, gj = tj0 - 1 + hj;
        float4 v = make_float4(0.f, 0.f, 0.f, 0.f);
        if (gi >= 0 && gi < K && gj >= 0 && gj < K)
            v = ((const float4*)(in + inB + (size_t)(gi * K + gj) * 64))[part];
        ((float4*)(Xs + node * 64))[part] = v;
    }
    __syncthreads();

    // Hs = r(src) * Xs @ W   (16 threads per node, 4 channels each)
    {
        const int lane16 = tid & 15, grp = tid >> 4;
        for (int node = grp; node < HN; node += 16) {
            int hi = node / HW, hj = node - hi * HW;
            float r = rdeg(ti0 - 1 + hi, tj0 - 1 + hj, K);
            const float* xr = Xs + node * 64;
            float4 acc = make_float4(0.f, 0.f, 0.f, 0.f);
#pragma unroll 16
            for (int k = 0; k < 64; k++) {
                float xv = xr[k];
                float4 w = ((const float4*)(Ws + k * 64))[lane16];
                acc.x = fmaf(xv, w.x, acc.x);
                acc.y = fmaf(xv, w.y, acc.y);
                acc.z = fmaf(xv, w.z, acc.z);
                acc.w = fmaf(xv, w.w, acc.w);
            }
            acc.x *= r; acc.y *= r; acc.z *= r; acc.w *= r;
            ((float4*)(Hs + node * 64))[lane16] = acc;
        }
    }
    __syncthreads();

    // stencil + inorm + (residual) + celu, one warp per node
    const int warp = tid >> 5, lane = tid & 31;
    for (int nd = warp; nd < TI * TJ; nd += 8) {
        int li = nd / TJ, lj = nd - li * TJ;
        int gi = ti0 + li, gj = tj0 + lj;
        if (gi >= REG || gj >= REG) continue;   // clamped tiles (non-POOL, K=25)
        const int c0 = lane, c1 = lane + 32;
        float a0 = 0.f, a1 = 0.f;
#pragma unroll
        for (int di = 0; di < 3; di++)
#pragma unroll
            for (int dj = 0; dj < 3; dj++) {
                const float* h = Hs + ((li + di) * HW + (lj + dj)) * 64;
                a0 += h[c0]; a1 += h[c1];
            }
        float r = rdeg(gi, gj, K);
        a0 = fmaf(a0, r, Bs[c0]);
        a1 = fmaf(a1, r, Bs[c1]);
        float s = a0 + a1, sq = a0 * a0 + a1 * a1;
#pragma unroll
        for (int o = 16; o; o >>= 1) {
            s  += __shfl_xor_sync(0xffffffffu, s,  o);
            sq += __shfl_xor_sync(0xffffffffu, sq, o);
        }
        float mean = s * (1.f / 64.f);
        float var  = sq * (1.f / 64.f) - mean * mean;
        float inv  = rsqrtf(var + 1e-5f);
        float y0 = (a0 - mean) * inv;
        float y1 = (a1 - mean) * inv;
        if (RES) {
            const float* rp = resid + inB + (size_t)(gi * K + gj) * 64;
            y0 += rp[c0]; y1 += rp[c1];
        }
        y0 = y0 > 0.f ? y0 : expm1f(y0);
        y1 = y1 > 0.f ? y1 : expm1f(y1);
        if (!POOL) {
            float* op = out + inB + (size_t)(gi * K + gj) * 64;
            op[c0] = y0; op[c1] = y1;
        } else {
            float* yp = Ys + nd * 64;
            yp[c0] = y0; yp[c1] = y1;
        }
    }

    if (POOL) {
        __syncthreads();
        constexpr int KP = K / 2;
        constexpr int PT = (TI / 2) * (TJ / 2);
        const size_t outB = (size_t)b * KP * KP * 64;
        for (int q = tid; q < PT * 64; q += 256) {
            int pn = q >> 6, c = q & 63;
            int pi = pn / (TJ / 2), pj = pn - pi * (TJ / 2);
            int li = pi * 2, lj = pj * 2;
            float m0 = fmaxf(Ys[(li * TJ + lj) * 64 + c],
                             Ys[(li * TJ + lj + 1) * 64 + c]);
            float m1 = fmaxf(Ys[((li + 1) * TJ + lj) * 64 + c],
                             Ys[((li + 1) * TJ + lj + 1) * 64 + c]);
            int gpi = ti0 / 2 + pi, gpj = tj0 / 2 + pj;
            out[outB + (size_t)(gpi * KP + gpj) * 64 + c] = fmaxf(m0, m1);
        }
    }
}

// ---------------------------------------------------------------------------
// G = W @ W^T  (M=256, K=Nf).  16x16 output tile per CTA, grid 16x16.
// ---------------------------------------------------------------------------
__global__ void k_gram(const float* __restrict__ W, int Nf, float* __restrict__ G) {
    __shared__ float As[16][65], Bs[16][65];
    const int tid = threadIdx.x;
    const int ty = tid >> 4, tx = tid & 15;
    const int i0 = blockIdx.y * 16, j0 = blockIdx.x * 16;
    float acc = 0.f;
    for (int kt = 0; kt < Nf; kt += 64) {
        for (int q = tid; q < 1024; q += 256) {
            int r = q >> 6, c = q & 63;
            As[r][c] = W[(size_t)(i0 + r) * Nf + kt + c];
            Bs[r][c] = W[(size_t)(j0 + r) * Nf + kt + c];
        }
        __syncthreads();
#pragma unroll 16
        for (int k = 0; k < 64; k++)
            acc = fmaf(As[ty][k], Bs[tx][k], acc);
        __syncthreads();
    }
    G[(i0 + ty) * 256 + (j0 + tx)] = acc;
}

__device__ __forceinline__ float blockReduceSum256(float x, float* red) {
#pragma unroll
    for (int o = 16; o; o >>= 1) x += __shfl_xor_sync(0xffffffffu, x, o);
    if ((threadIdx.x & 31) == 0) red[threadIdx.x >> 5] = x;
    __syncthreads();
    float tot = 0.f;
#pragma unroll
    for (int i = 0; i < 8; i++) tot += red[i];
    return tot;   // every thread gets the same value
}

// ---------------------------------------------------------------------------
// Power iteration via G = WW^T:  u_k = normalize(G u_{k-1}) == reference's u_k.
// 29 iterations give u_29; v_30 = normalize(W^T u_29); sigma = |Wv|^2/(|Wv|+eps).
// grid.x=0 -> lw1 (Nf=2304), grid.x=1 -> lw2 (Nf=256).  256 threads.
// ---------------------------------------------------------------------------
__global__ void k_power(const float* __restrict__ lw1, const float* __restrict__ lw2,
                        const float* __restrict__ G1, const float* __restrict__ G2,
                        float* __restrict__ sig) {
    const float* G  = blockIdx.x == 0 ? G1 : G2;
    const float* W  = blockIdx.x == 0 ? lw1 : lw2;
    const int   Nf  = blockIdx.x == 0 ? 2304 : 256;
    __shared__ float u[256];
    __shared__ float v[2304];
    __shared__ float red[32];
    const int tid = threadIdx.x;
    u[tid] = 1.f / 16.f;                 // ones / sqrt(256)
    __syncthreads();
    for (int it = 0; it < 29; it++) {
        const float* gr = G + tid * 256;
        float acc = 0.f;
#pragma unroll 8
        for (int j = 0; j < 256; j++) acc = fmaf(gr[j], u[j], acc);
        float nrm = blockReduceSum256(acc * acc, red);
        __syncthreads();
        u[tid] = acc / (sqrtf(nrm) + 1e-12f);
        __syncthreads();
    }
    // v = normalize(W^T u)
    float ss = 0.f;
    for (int j0 = 0; j0 < Nf; j0 += 256) {
        float acc = 0.f;
#pragma unroll 8
        for (int i = 0; i < 256; i++) acc = fmaf(W[(size_t)i * Nf + j0 + tid], u[i], acc);
        v[j0 + tid] = acc;
        ss += acc * acc;
    }
    float nv = blockReduceSum256(ss, red);
    __syncthreads();
    float inv = 1.f / (sqrtf(nv) + 1e-12f);
    for (int j0 = tid; j0 < Nf; j0 += 256) v[j0] *= inv;
    __syncthreads();
    // w = W v; sigma = |w|^2 / (|w| + eps)
    const float* wr = W + (size_t)tid * Nf;
    float acc = 0.f;
#pragma unroll 8
    for (int j = 0; j < Nf; j++) acc = fmaf(wr[j], v[j], acc);
    float nw = blockReduceSum256(acc * acc, red);
    if (tid == 0) sig[blockIdx.x] = nw / (sqrtf(nw) + 1e-12f);
}

// ---------------------------------------------------------------------------
// h1 = celu(F @ W1^T / sigma1 + b1)   F:[64,2304], W1:[256,2304]
// grid (4 ogroups of 64, 16 bgroups of 4).  256 threads = 64 outs x 4 k-splits.
// ---------------------------------------------------------------------------
__global__ void k_lin1(const float* __restrict__ F, const float* __restrict__ W,
                       const float* __restrict__ bias, const float* __restrict__ sig,
                       float* __restrict__ out) {
    __shared__ float Fs[4 * 2304];
    __shared__ float part[4][4][64];
    const int tid = threadIdx.x;
    const int og = blockIdx.x, bg = blockIdx.y;
    const float4* src = (const float4*)(F + (size_t)bg * 4 * 2304);
    for (int q = tid; q < 2304; q += 256) ((float4*)Fs)[q] = src[q];
    __syncthreads();
    const int ol = tid & 63, ks = tid >> 6;
    const int o = og * 64 + ol;
    const float* wr = W + (size_t)o * 2304 + ks * 576;
    const float* fb = Fs + ks * 576;
    float a0 = 0.f, a1 = 0.f, a2 = 0.f, a3 = 0.f;
#pragma unroll 4
    for (int k = 0; k < 576; k++) {
        float w = wr[k];
        a0 = fmaf(w, fb[k],        a0);
        a1 = fmaf(w, fb[2304 + k], a1);
        a2 = fmaf(w, fb[4608 + k], a2);
        a3 = fmaf(w, fb[6912 + k], a3);
    }
    part[ks][0][ol] = a0; part[ks][1][ol] = a1;
    part[ks][2][ol] = a2; part[ks][3][ol] = a3;
    __syncthreads();
    if (ks == 0) {
        float s0 = sig[0], bo = bias[o];
#pragma unroll
        for (int bb = 0; bb < 4; bb++) {
            float z = part[0][bb][ol] + part[1][bb][ol] + part[2][bb][ol] + part[3][bb][ol];
            z = z / s0 + bo;
            out[(size_t)(bg * 4 + bb) * 256 + o] = z > 0.f ? z : expm1f(z);
        }
    }
}

// out = celu(h1 @ W2^T / sigma2 + b2)  -> d_out [64,256]
__global__ void k_lin2(const float* __restrict__ h1, const float* __restrict__ W,
                       const float* __restrict__ bias, const float* __restrict__ sig,
                       float* __restrict__ out) {
    const int b = blockIdx.x, o = threadIdx.x;
    __shared__ float hs[256];
    hs[o] = h1[b * 256 + o];
    __syncthreads();
    const float* wr = W + o * 256;
    float acc = 0.f;
#pragma unroll 8
    for (int k = 0; k < 256; k++) acc = fmaf(wr[k], hs[k], acc);
    acc = acc / sig[1] + bias[o];
    out[b * 256 + o] = acc > 0.f ? acc : expm1f(acc);
}

// ---------------------------------------------------------------------------
extern "C" void kernel_launch(void* const* d_in, const int* in_sizes, int n_in,
                              void* d_out, int out_size) {
    const float* x      = (const float*)d_in[0];
    const float* w_init = (const float*)d_in[1];
    const float* b_init = (const float*)d_in[2];
    const float* w11 = (const float*)d_in[3];  const float* b11 = (const float*)d_in[4];
    const float* w12 = (const float*)d_in[5];  const float* b12 = (const float*)d_in[6];
    const float* w21 = (const float*)d_in[7];  const float* b21 = (const float*)d_in[8];
    const float* w22 = (const float*)d_in[9];  const float* b22 = (const float*)d_in[10];
    const float* w31 = (const float*)d_in[11]; const float* b31 = (const float*)d_in[12];
    const float* w32 = (const float*)d_in[13]; const float* b32 = (const float*)d_in[14];
    const float* lw1 = (const float*)d_in[15]; const float* lb1 = (const float*)d_in[16];
    const float* lw2 = (const float*)d_in[17]; const float* lb2 = (const float*)d_in[18];

    float *pA, *pX1, *pP1, *pP2, *pF, *pG1, *pG2, *pSig, *pH1;
    cudaGetSymbolAddress((void**)&pA,  g_A);
    cudaGetSymbolAddress((void**)&pX1, g_X1);
    cudaGetSymbolAddress((void**)&pP1, g_P1);
    cudaGetSymbolAddress((void**)&pP2, g_P2);
    cudaGetSymbolAddress((void**)&pF,  g_F);
    cudaGetSymbolAddress((void**)&pG1, g_G1);
    cudaGetSymbolAddress((void**)&pG2, g_G2);
    cudaGetSymbolAddress((void**)&pSig, g_Sig);
    cudaGetSymbolAddress((void**)&pH1, g_H1);

    // dynamic smem sizes (bytes)
    const size_t s1a = (4160 + 144 * 64 * 2) * sizeof(float);               // 90368
    const size_t s1b = (4160 + 144 * 64 * 2 + 100 * 64) * sizeof(float);    // 115968
    const size_t s2a = (4160 + 121 * 64 * 2) * sizeof(float);               // 78592
    const size_t s2b = (4160 + 100 * 64 * 2 + 64 * 64) * sizeof(float);     // 84224
    const size_t s3a = (4160 +  64 * 64 * 2) * sizeof(float);               // 49408
    const size_t s3b = (4160 +  64 * 64 * 2 + 36 * 64) * sizeof(float);     // 58624

    cudaFuncSetAttribute(k_gcn<50,10,10,false,false>, cudaFuncAttributeMaxDynamicSharedMemorySize, (int)s1a);
    cudaFuncSetAttribute(k_gcn<50,10,10,true, true >, cudaFuncAttributeMaxDynamicSharedMemorySize, (int)s1b);
    cudaFuncSetAttribute(k_gcn<25, 9, 9,false,false>, cudaFuncAttributeMaxDynamicSharedMemorySize, (int)s2a);
    cudaFuncSetAttribute(k_gcn<25, 8, 8,true, true >, cudaFuncAttributeMaxDynamicSharedMemorySize, (int)s2b);
    cudaFuncSetAttribute(k_gcn<12, 6, 6,false,false>, cudaFuncAttributeMaxDynamicSharedMemorySize, (int)s3a);
    cudaFuncSetAttribute(k_gcn<12, 6, 6,true, true >, cudaFuncAttributeMaxDynamicSharedMemorySize, (int)s3b);

    // init GCN
    k_init<<<(NB * 2500 + 255) / 256, 256>>>(x, w_init, b_init, pA);

    // stage 1 (k=50)
    k_gcn<50,10,10,false,false><<<dim3(5,5,NB), 256, s1a>>>(pA,  nullptr, w11, b11, pX1);
    k_gcn<50,10,10,true, true ><<<dim3(5,5,NB), 256, s1b>>>(pX1, pA,      w12, b12, pP1);
    // stage 2 (k=25)
    k_gcn<25, 9, 9,false,false><<<dim3(3,3,NB), 256, s2a>>>(pP1, nullptr, w21, b21, pX1);
    k_gcn<25, 8, 8,true, true ><<<dim3(3,3,NB), 256, s2b>>>(pX1, pP1,     w22, b22, pP2);
    // stage 3 (k=12)
    k_gcn<12, 6, 6,false,false><<<dim3(2,2,NB), 256, s3a>>>(pP2, nullptr, w31, b31, pX1);
    k_gcn<12, 6, 6,true, true ><<<dim3(2,2,NB), 256, s3b>>>(pX1, pP2,     w32, b32, pF);

    // spectral-norm head
    k_gram<<<dim3(16,16), 256>>>(lw1, 2304, pG1);
    k_gram<<<dim3(16,16), 256>>>(lw2,  256, pG2);
    k_power<<<2, 256>>>(lw1, lw2, pG1, pG2, pSig);
    k_lin1<<<dim3(4,16), 256>>>(pF, lw1, lb1, pSig, pH1);
    k_lin2<<<64, 256>>>(pH1, lw2, lb2, pSig, (float*)d_out);
}

// round 12
// speedup vs baseline: 1.9372x; 1.9372x over previous
#include <cuda_runtime.h>
#include <cuda_bf16.h>
#include <math.h>

// ---------------------------------------------------------------------------
//   x [64,2500,1] -> initGCN -> [64,2500,64]
//   block(k=50) -> [64,625,64]; block(k=25) -> [64,144,64]; block(k=12) -> [64,36,64]
//   flatten [64,2304] -> SN-linear(256) -> celu -> SN-linear(256) -> celu
// Each GCN layer = GEMM kernel (H = r(src)*(X@W)) + stencil kernel
// (3x3 sum * r(dst) + bias -> inorm -> [+res] -> celu -> [pool]).
// ---------------------------------------------------------------------------

#define NB 64
#define NC 64

__device__ float g_A [64*2500*64];
__device__ float g_X1[64*2500*64];
__device__ float g_H [64*2500*64];
__device__ float g_P1[64*625*64];
__device__ float g_P2[64*144*64];
__device__ float g_F [64*36*64];
__device__ float g_G1[256*256];
__device__ float g_G2[256*256];
__device__ float g_Sig[2];
__device__ float g_H1[64*256];

__device__ __forceinline__ float rdeg(int i, int j, int k) {
    int ci = 1 + (i > 0) + (i < k - 1);
    int cj = 1 + (j > 0) + (j < k - 1);
    return rsqrtf((float)(ci * cj));
}

// ---------------------------------------------------------------------------
// init GCN (Cin=1): s[b,n] = r(n)*sum_nbr r(nbr)*x[b,nbr]; out = s*w0 + b0
// ---------------------------------------------------------------------------
__global__ void k_init(const float* __restrict__ x, const float* __restrict__ w0,
                       const float* __restrict__ b0, float* __restrict__ out) {
    __shared__ float ws[64], bs[64];
    if (threadIdx.x < 64)       ws[threadIdx.x]      = w0[threadIdx.x];
    else if (threadIdx.x < 128) bs[threadIdx.x - 64] = b0[threadIdx.x - 64];
    __syncthreads();
    int idx = blockIdx.x * 256 + threadIdx.x;
    if (idx >= NB * 2500) return;
    int b = idx / 2500, n = idx - b * 2500;
    int i = n / 50, j = n - i * 50;
    float s = 0.f;
#pragma unroll
    for (int di = -1; di <= 1; di++)
#pragma unroll
        for (int dj = -1; dj <= 1; dj++) {
            int ii = i + di, jj = j + dj;
            if (ii >= 0 && ii < 50 && jj >= 0 && jj < 50)
                s += rdeg(ii, jj, 50) * x[b * 2500 + ii * 50 + jj];
        }
    s *= rdeg(i, j, 50);
    float4* op = (float4*)(out + (size_t)idx * 64);
#pragma unroll
    for (int q = 0; q < 16; q++) {
        float4 w = ((float4*)ws)[q], bb = ((float4*)bs)[q];
        op[q] = make_float4(fmaf(s, w.x, bb.x), fmaf(s, w.y, bb.y),
                            fmaf(s, w.z, bb.z), fmaf(s, w.w, bb.w));
    }
}

// ---------------------------------------------------------------------------
// GEMM: H[m,:] = r(m) * (X[m,:] @ W)   X:[M,64] W:[64,64]
// CTA: 128 rows x 64 cols, 256 threads, thread computes 8 rows x 4 cols.
// ---------------------------------------------------------------------------
template<int KSIDE>
__global__ __launch_bounds__(256) void k_gemm(const float* __restrict__ X,
                                              const float* __restrict__ W,
                                              float* __restrict__ H, int M) {
    extern __shared__ float sg[];
    float* Xs = sg;              // 128*64
    float* Ws = sg + 128 * 64;   // 64*64
    const int tid = threadIdx.x;
    const int m0 = blockIdx.x * 128;
    for (int q = tid; q < 1024; q += 256)
        ((float4*)Ws)[q] = ((const float4*)W)[q];
    for (int q = tid; q < 2048; q += 256) {
        int row = q >> 4;
        int gr = m0 + row;
        float4 v = make_float4(0.f, 0.f, 0.f, 0.f);
        if (gr < M) v = ((const float4*)(X + (size_t)gr * 64))[q & 15];
        ((float4*)Xs)[q] = v;
    }
    __syncthreads();
    const int tx = tid & 15, ty = tid >> 4;
    const int r0 = ty * 8;
    float acc[8][4];
#pragma unroll
    for (int i = 0; i < 8; i++)
        acc[i][0] = acc[i][1] = acc[i][2] = acc[i][3] = 0.f;
    const float4* W4 = (const float4*)Ws;
#pragma unroll 4
    for (int k = 0; k < 64; k += 2) {
        float4 w0 = W4[k * 16 + tx];
        float4 w1 = W4[k * 16 + 16 + tx];
#pragma unroll
        for (int i = 0; i < 8; i++) {
            float2 a = *(const float2*)(Xs + (r0 + i) * 64 + k);
            acc[i][0] = fmaf(a.y, w1.x, fmaf(a.x, w0.x, acc[i][0]));
            acc[i][1] = fmaf(a.y, w1.y, fmaf(a.x, w0.y, acc[i][1]));
            acc[i][2] = fmaf(a.y, w1.z, fmaf(a.x, w0.z, acc[i][2]));
            acc[i][3] = fmaf(a.y, w1.w, fmaf(a.x, w0.w, acc[i][3]));
        }
    }
    constexpr int KK = KSIDE * KSIDE;
#pragma unroll
    for (int i = 0; i < 8; i++) {
        int gr = m0 + r0 + i;
        if (gr >= M) break;
        int n  = gr % KK;
        int gi = n / KSIDE, gj = n - gi * KSIDE;
        float r = rdeg(gi, gj, KSIDE);
        ((float4*)(H + (size_t)gr * 64))[tx] =
            make_float4(acc[i][0] * r, acc[i][1] * r, acc[i][2] * r, acc[i][3] * r);
    }
}

// ---------------------------------------------------------------------------
// Stencil: y = celu(inorm(r(dst)*sum3x3(H) + bias) [+res]) [then 2x2 maxpool]
// ---------------------------------------------------------------------------
template<int K, int TI, int TJ, bool POOL, bool RES>
__global__ __launch_bounds__(256) void k_stencil(const float* __restrict__ Hin,
                                                 const float* __restrict__ resid,
                                                 const float* __restrict__ bias,
                                                 float* __restrict__ out) {
    constexpr int HW = TJ + 2;
    constexpr int HN = (TI + 2) * (TJ + 2);
    constexpr int REG = POOL ? (K / 2) * 2 : K;

    extern __shared__ float sm[];
    float* Bs = sm;              // 64
    float* Hs = sm + 64;         // HN*64
    float* Ys = Hs + HN * 64;    // TI*TJ*64 (POOL only)

    const int tid = threadIdx.x;
    const int b = blockIdx.z;
    const int ti0 = blockIdx.y * TI, tj0 = blockIdx.x * TJ;
    const size_t inB = (size_t)b * K * K * 64;

    if (tid < 16) ((float4*)Bs)[tid] = ((const float4*)bias)[tid];
    for (int q = tid; q < HN * 16; q += 256) {
        int node = q >> 4, part = q & 15;
        int hi = node / HW, hj = node - hi * HW;
        int gi = ti0 - 1 + hi, gj = tj0 - 1 + hj;
        float4 v = make_float4(0.f, 0.f, 0.f, 0.f);
        if (gi >= 0 && gi < K && gj >= 0 && gj < K)
            v = ((const float4*)(Hin + inB + (size_t)(gi * K + gj) * 64))[part];
        ((float4*)(Hs + node * 64))[part] = v;
    }
    __syncthreads();

    const int warp = tid >> 5, lane = tid & 31;
    for (int nd = warp; nd < TI * TJ; nd += 8) {
        int li = nd / TJ, lj = nd - li * TJ;
        int gi = ti0 + li, gj = tj0 + lj;
        if (gi >= REG || gj >= REG) continue;
        const int c0 = lane, c1 = lane + 32;
        float a0 = 0.f, a1 = 0.f;
#pragma unroll
        for (int di = 0; di < 3; di++)
#pragma unroll
            for (int dj = 0; dj < 3; dj++) {
                const float* h = Hs + ((li + di) * HW + (lj + dj)) * 64;
                a0 += h[c0]; a1 += h[c1];
            }
        float r = rdeg(gi, gj, K);
        a0 = fmaf(a0, r, Bs[c0]);
        a1 = fmaf(a1, r, Bs[c1]);
        float s = a0 + a1, sq = a0 * a0 + a1 * a1;
#pragma unroll
        for (int o = 16; o; o >>= 1) {
            s  += __shfl_xor_sync(0xffffffffu, s,  o);
            sq += __shfl_xor_sync(0xffffffffu, sq, o);
        }
        float mean = s * (1.f / 64.f);
        float var  = sq * (1.f / 64.f) - mean * mean;
        float inv  = rsqrtf(var + 1e-5f);
        float y0 = (a0 - mean) * inv;
        float y1 = (a1 - mean) * inv;
        if (RES) {
            const float* rp = resid + inB + (size_t)(gi * K + gj) * 64;
            y0 += rp[c0]; y1 += rp[c1];
        }
        y0 = y0 > 0.f ? y0 : expm1f(y0);
        y1 = y1 > 0.f ? y1 : expm1f(y1);
        if (!POOL) {
            float* op = out + inB + (size_t)(gi * K + gj) * 64;
            op[c0] = y0; op[c1] = y1;
        } else {
            float* yp = Ys + nd * 64;
            yp[c0] = y0; yp[c1] = y1;
        }
    }

    if (POOL) {
        __syncthreads();
        constexpr int KP = K / 2;
        constexpr int PT = (TI / 2) * (TJ / 2);
        const size_t outB = (size_t)b * KP * KP * 64;
        for (int q = tid; q < PT * 64; q += 256) {
            int pn = q >> 6, c = q & 63;
            int pi = pn / (TJ / 2), pj = pn - pi * (TJ / 2);
            int li = pi * 2, lj = pj * 2;
            float m0 = fmaxf(Ys[(li * TJ + lj) * 64 + c],
                             Ys[(li * TJ + lj + 1) * 64 + c]);
            float m1 = fmaxf(Ys[((li + 1) * TJ + lj) * 64 + c],
                             Ys[((li + 1) * TJ + lj + 1) * 64 + c]);
            int gpi = ti0 / 2 + pi, gpj = tj0 / 2 + pj;
            out[outB + (size_t)(gpi * KP + gpj) * 64 + c] = fmaxf(m0, m1);
        }
    }
}

// ---------------------------------------------------------------------------
// G += W[i0:i0+64, k0:k0+128] @ W[j0:j0+64, k0:k0+128]^T  (split-K, atomic)
// grid (4, 4, Nf/128), 256 threads, thread computes 4x4.
// ---------------------------------------------------------------------------
__global__ __launch_bounds__(256) void k_gram(const float* __restrict__ W, int Nf,
                                              float* __restrict__ G) {
    extern __shared__ float sh[];
    float* As = sh;              // 64*130
    float* Bsm = sh + 64 * 130;  // 64*130
    const int tid = threadIdx.x;
    const int j0 = blockIdx.x * 64, i0 = blockIdx.y * 64, k0 = blockIdx.z * 128;
    for (int q = tid; q < 2048; q += 256) {
        int r = q >> 5, c = (q & 31) * 4;
        float4 v = *(const float4*)(W + (size_t)(i0 + r) * Nf + k0 + c);
        As[r * 130 + c] = v.x; As[r * 130 + c + 1] = v.y;
        As[r * 130 + c + 2] = v.z; As[r * 130 + c + 3] = v.w;
        float4 u = *(const float4*)(W + (size_t)(j0 + r) * Nf + k0 + c);
        Bsm[r * 130 + c] = u.x; Bsm[r * 130 + c + 1] = u.y;
        Bsm[r * 130 + c + 2] = u.z; Bsm[r * 130 + c + 3] = u.w;
    }
    __syncthreads();
    const int tx = tid & 15, ty = tid >> 4;
    float acc[4][4];
#pragma unroll
    for (int i = 0; i < 4; i++)
        acc[i][0] = acc[i][1] = acc[i][2] = acc[i][3] = 0.f;
#pragma unroll 4
    for (int k = 0; k < 128; k += 2) {
        float2 a[4], bb[4];
#pragma unroll
        for (int i = 0; i < 4; i++) a[i]  = *(const float2*)(As  + (ty * 4 + i) * 130 + k);
#pragma unroll
        for (int j = 0; j < 4; j++) bb[j] = *(const float2*)(Bsm + (tx * 4 + j) * 130 + k);
#pragma unroll
        for (int i = 0; i < 4; i++)
#pragma unroll
            for (int j = 0; j < 4; j++)
                acc[i][j] = fmaf(a[i].y, bb[j].y, fmaf(a[i].x, bb[j].x, acc[i][j]));
    }
#pragma unroll
    for (int i = 0; i < 4; i++)
#pragma unroll
        for (int j = 0; j < 4; j++)
            atomicAdd(&G[(size_t)(i0 + ty * 4 + i) * 256 + j0 + tx * 4 + j], acc[i][j]);
}

__device__ __forceinline__ float blockReduceSum256(float x, float* red) {
#pragma unroll
    for (int o = 16; o; o >>= 1) x += __shfl_xor_sync(0xffffffffu, x, o);
    if ((threadIdx.x & 31) == 0) red[threadIdx.x >> 5] = x;
    __syncthreads();
    float tot = 0.f;
#pragma unroll
    for (int i = 0; i < 8; i++) tot += red[i];
    return tot;
}

// ---------------------------------------------------------------------------
// Power iteration: u <- normalize(G u) x29 (G symmetric -> coalesced column
// reads), then v = normalize(W^T u), sigma = |Wv|^2/(|Wv|+1e-12).
// ---------------------------------------------------------------------------
__global__ void k_power(const float* __restrict__ lw1, const float* __restrict__ lw2,
                        const float* __restrict__ G1, const float* __restrict__ G2,
                        float* __restrict__ sig) {
    const float* G  = blockIdx.x == 0 ? G1 : G2;
    const float* W  = blockIdx.x == 0 ? lw1 : lw2;
    const int   Nf  = blockIdx.x == 0 ? 2304 : 256;
    __shared__ float u[256];
    __shared__ float v[2304];
    __shared__ float red[32];
    const int tid = threadIdx.x;
    u[tid] = 1.f / 16.f;
    __syncthreads();
    for (int it = 0; it < 29; it++) {
        float a0 = 0.f, a1 = 0.f, a2 = 0.f, a3 = 0.f;
#pragma unroll 8
        for (int j = 0; j < 256; j += 4) {           // G[i][j]==G[j][i]
            a0 = fmaf(G[(j + 0) * 256 + tid], u[j + 0], a0);
            a1 = fmaf(G[(j + 1) * 256 + tid], u[j + 1], a1);
            a2 = fmaf(G[(j + 2) * 256 + tid], u[j + 2], a2);
            a3 = fmaf(G[(j + 3) * 256 + tid], u[j + 3], a3);
        }
        float acc = (a0 + a1) + (a2 + a3);
        float nrm = blockReduceSum256(acc * acc, red);
        __syncthreads();
        u[tid] = acc / (sqrtf(nrm) + 1e-12f);
        __syncthreads();
    }
    float ss = 0.f;
    for (int j0 = 0; j0 < Nf; j0 += 256) {
        float acc = 0.f;
#pragma unroll 8
        for (int i = 0; i < 256; i++)
            acc = fmaf(W[(size_t)i * Nf + j0 + tid], u[i], acc);
        v[j0 + tid] = acc;
        ss += acc * acc;
    }
    float nv = blockReduceSum256(ss, red);
    __syncthreads();
    float inv = 1.f / (sqrtf(nv) + 1e-12f);
    for (int j0 = tid; j0 < Nf; j0 += 256) v[j0] *= inv;
    __syncthreads();
    const float* wr = W + (size_t)tid * Nf;
    float acc = 0.f;
#pragma unroll 8
    for (int j = 0; j < Nf; j++) acc = fmaf(wr[j], v[j], acc);
    float nw = blockReduceSum256(acc * acc, red);
    if (tid == 0) sig[blockIdx.x] = nw / (sqrtf(nw) + 1e-12f);
}

// ---------------------------------------------------------------------------
// h1 = celu(F @ W1^T / sigma1 + b1)   F:[64,2304], W1:[256,2304]
// ---------------------------------------------------------------------------
__global__ void k_lin1(const float* __restrict__ F, const float* __restrict__ W,
                       const float* __restrict__ bias, const float* __restrict__ sig,
                       float* __restrict__ out) {
    __shared__ float Fs[4 * 2304];
    __shared__ float part[4][4][64];
    const int tid = threadIdx.x;
    const int og = blockIdx.x, bg = blockIdx.y;
    const float4* src = (const float4*)(F + (size_t)bg * 4 * 2304);
    for (int q = tid; q < 2304; q += 256) ((float4*)Fs)[q] = src[q];
    __syncthreads();
    const int ol = tid & 63, ks = tid >> 6;
    const int o = og * 64 + ol;
    const float* wr = W + (size_t)o * 2304 + ks * 576;
    const float* fb = Fs + ks * 576;
    float a0 = 0.f, a1 = 0.f, a2 = 0.f, a3 = 0.f;
#pragma unroll 4
    for (int k = 0; k < 576; k++) {
        float w = wr[k];
        a0 = fmaf(w, fb[k],        a0);
        a1 = fmaf(w, fb[2304 + k], a1);
        a2 = fmaf(w, fb[4608 + k], a2);
        a3 = fmaf(w, fb[6912 + k], a3);
    }
    part[ks][0][ol] = a0; part[ks][1][ol] = a1;
    part[ks][2][ol] = a2; part[ks][3][ol] = a3;
    __syncthreads();
    if (ks == 0) {
        float s0 = sig[0], bo = bias[o];
#pragma unroll
        for (int bb = 0; bb < 4; bb++) {
            float z = part[0][bb][ol] + part[1][bb][ol] + part[2][bb][ol] + part[3][bb][ol];
            z = z / s0 + bo;
            out[(size_t)(bg * 4 + bb) * 256 + o] = z > 0.f ? z : expm1f(z);
        }
    }
}

__global__ void k_lin2(const float* __restrict__ h1, const float* __restrict__ W,
                       const float* __restrict__ bias, const float* __restrict__ sig,
                       float* __restrict__ out) {
    const int b = blockIdx.x, o = threadIdx.x;
    __shared__ float hs[256];
    hs[o] = h1[b * 256 + o];
    __syncthreads();
    const float* wr = W + o * 256;
    float acc = 0.f;
#pragma unroll 8
    for (int k = 0; k < 256; k++) acc = fmaf(wr[k], hs[k], acc);
    acc = acc / sig[1] + bias[o];
    out[b * 256 + o] = acc > 0.f ? acc : expm1f(acc);
}

// ---------------------------------------------------------------------------
extern "C" void kernel_launch(void* const* d_in, const int* in_sizes, int n_in,
                              void* d_out, int out_size) {
    const float* x      = (const float*)d_in[0];
    const float* w_init = (const float*)d_in[1];
    const float* b_init = (const float*)d_in[2];
    const float* w11 = (const float*)d_in[3];  const float* b11 = (const float*)d_in[4];
    const float* w12 = (const float*)d_in[5];  const float* b12 = (const float*)d_in[6];
    const float* w21 = (const float*)d_in[7];  const float* b21 = (const float*)d_in[8];
    const float* w22 = (const float*)d_in[9];  const float* b22 = (const float*)d_in[10];
    const float* w31 = (const float*)d_in[11]; const float* b31 = (const float*)d_in[12];
    const float* w32 = (const float*)d_in[13]; const float* b32 = (const float*)d_in[14];
    const float* lw1 = (const float*)d_in[15]; const float* lb1 = (const float*)d_in[16];
    const float* lw2 = (const float*)d_in[17]; const float* lb2 = (const float*)d_in[18];

    float *pA, *pX1, *pH, *pP1, *pP2, *pF, *pG1, *pG2, *pSig, *pH1;
    cudaGetSymbolAddress((void**)&pA,  g_A);
    cudaGetSymbolAddress((void**)&pX1, g_X1);
    cudaGetSymbolAddress((void**)&pH,  g_H);
    cudaGetSymbolAddress((void**)&pP1, g_P1);
    cudaGetSymbolAddress((void**)&pP2, g_P2);
    cudaGetSymbolAddress((void**)&pF,  g_F);
    cudaGetSymbolAddress((void**)&pG1, g_G1);
    cudaGetSymbolAddress((void**)&pG2, g_G2);
    cudaGetSymbolAddress((void**)&pSig, g_Sig);
    cudaGetSymbolAddress((void**)&pH1, g_H1);

    const size_t sg   = (128 * 64 + 64 * 64) * sizeof(float);           // 49152
    const size_t sgr  = 2 * 64 * 130 * sizeof(float);                   // 66560
    const size_t s1a = (64 + 144 * 64) * sizeof(float);                 // 37120
    const size_t s1b = (64 + 144 * 64 + 100 * 64) * sizeof(float);      // 62720
    const size_t s2a = (64 + 121 * 64) * sizeof(float);                 // 31232
    const size_t s2b = (64 + 100 * 64 + 64 * 64) * sizeof(float);       // 42240
    const size_t s3a = (64 +  64 * 64) * sizeof(float);                 // 16640
    const size_t s3b = (64 +  64 * 64 + 36 * 64) * sizeof(float);       // 25856

    cudaFuncSetAttribute(k_gemm<50>, cudaFuncAttributeMaxDynamicSharedMemorySize, (int)sg);
    cudaFuncSetAttribute(k_gemm<25>, cudaFuncAttributeMaxDynamicSharedMemorySize, (int)sg);
    cudaFuncSetAttribute(k_gemm<12>, cudaFuncAttributeMaxDynamicSharedMemorySize, (int)sg);
    cudaFuncSetAttribute(k_gram,     cudaFuncAttributeMaxDynamicSharedMemorySize, (int)sgr);
    cudaFuncSetAttribute(k_stencil<50,10,10,false,false>, cudaFuncAttributeMaxDynamicSharedMemorySize, (int)s1a);
    cudaFuncSetAttribute(k_stencil<50,10,10,true, true >, cudaFuncAttributeMaxDynamicSharedMemorySize, (int)s1b);
    cudaFuncSetAttribute(k_stencil<25, 9, 9,false,false>, cudaFuncAttributeMaxDynamicSharedMemorySize, (int)s2a);
    cudaFuncSetAttribute(k_stencil<25, 8, 8,true, true >, cudaFuncAttributeMaxDynamicSharedMemorySize, (int)s2b);
    cudaFuncSetAttribute(k_stencil<12, 6, 6,false,false>, cudaFuncAttributeMaxDynamicSharedMemorySize, (int)s3a);
    cudaFuncSetAttribute(k_stencil<12, 6, 6,true, true >, cudaFuncAttributeMaxDynamicSharedMemorySize, (int)s3b);

    const int M1 = NB * 2500, M2 = NB * 625, M3 = NB * 144;

    k_init<<<(NB * 2500 + 255) / 256, 256>>>(x, w_init, b_init, pA);

    // stage 1 (k=50)
    k_gemm<50><<<(M1 + 127) / 128, 256, sg>>>(pA, w11, pH, M1);
    k_stencil<50,10,10,false,false><<<dim3(5,5,NB), 256, s1a>>>(pH, nullptr, b11, pX1);
    k_gemm<50><<<(M1 + 127) / 128, 256, sg>>>(pX1, w12, pH, M1);
    k_stencil<50,10,10,true, true ><<<dim3(5,5,NB), 256, s1b>>>(pH, pA, b12, pP1);
    // stage 2 (k=25)
    k_gemm<25><<<(M2 + 127) / 128, 256, sg>>>(pP1, w21, pH, M2);
    k_stencil<25, 9, 9,false,false><<<dim3(3,3,NB), 256, s2a>>>(pH, nullptr, b21, pX1);
    k_gemm<25><<<(M2 + 127) / 128, 256, sg>>>(pX1, w22, pH, M2);
    k_stencil<25, 8, 8,true, true ><<<dim3(3,3,NB), 256, s2b>>>(pH, pP1, b22, pP2);
    // stage 3 (k=12)
    k_gemm<12><<<(M3 + 127) / 128, 256, sg>>>(pP2, w31, pH, M3);
    k_stencil<12, 6, 6,false,false><<<dim3(2,2,NB), 256, s3a>>>(pH, nullptr, b31, pX1);
    k_gemm<12><<<(M3 + 127) / 128, 256, sg>>>(pX1, w32, pH, M3);
    k_stencil<12, 6, 6,true, true ><<<dim3(2,2,NB), 256, s3b>>>(pH, pP2, b32, pF);

    // spectral-norm head
    cudaMemsetAsync(pG1, 0, 256 * 256 * sizeof(float));
    cudaMemsetAsync(pG2, 0, 256 * 256 * sizeof(float));
    k_gram<<<dim3(4,4,18), 256, sgr>>>(lw1, 2304, pG1);
    k_gram<<<dim3(4,4, 2), 256, sgr>>>(lw2,  256, pG2);
    k_power<<<2, 256>>>(lw1, lw2, pG1, pG2, pSig);
    k_lin1<<<dim3(4,16), 256>>>(pF, lw1, lb1, pSig, pH1);
    k_lin2<<<64, 256>>>(pH1, lw2, lb2, pSig, (float*)d_out);
}

// round 13
// speedup vs baseline: 4.1747x; 2.1550x over previous
#include <cuda_runtime.h>
#include <cuda_bf16.h>
#include <math.h>

// ---------------------------------------------------------------------------
//   x [64,2500,1] -> initGCN (rank-1) -> stage1(k=50) -> [64,625,64]
//   stage2(k=25) -> [64,144,64]; stage3(k=12) -> [64,36,64]
//   flatten [64,2304] -> SN-linear(256) -> celu -> SN-linear(256) -> celu
// Stage-1 first GCN is rank-1 in the node dim: A = s (x) w0 + b0, so
// A@W11 = s (x) p + 1 (x) q with p=w0@W11, q=b0@W11, and the InstanceNorm
// statistics are closed-form in (alpha,beta). Eliminates one 1.3GF GEMM and
// 82MB of traffic. GEMMs use packed fma.rn.f32x2 (FFMA2, 2x scalar FFMA rate).
// ---------------------------------------------------------------------------

#define NB 64
#define NC 64

__device__ float g_s [64*2500];      // init GCN scalar field
__device__ float g_X1[64*2500*64];
__device__ float g_H [64*2500*64];
__device__ float g_P1[64*625*64];
__device__ float g_P2[64*144*64];
__device__ float g_F [64*36*64];
__device__ float g_G1[256*256];
__device__ float g_G2[256*256];
__device__ float g_Sig[2];
__device__ float g_H1[64*256];
__device__ float g_Par[160];         // p[64], q[64], 9 scalar moments

__device__ __forceinline__ float rdeg(int i, int j, int k) {
    int ci = 1 + (i > 0) + (i < k - 1);
    int cj = 1 + (j > 0) + (j < k - 1);
    return rsqrtf((float)(ci * cj));
}

// ---- packed f32x2 helpers --------------------------------------------------
__device__ __forceinline__ void fma2(unsigned long long& d,
                                     unsigned long long a, unsigned long long b) {
    asm("fma.rn.f32x2 %0, %1, %2, %0;" : "+l"(d) : "l"(a), "l"(b));
}
__device__ __forceinline__ unsigned long long pk2(float x) {
    unsigned long long d;
    asm("mov.b64 %0, {%1, %1};" : "=l"(d) : "f"(x));
    return d;
}
__device__ __forceinline__ float2 upk2(unsigned long long v) {
    float2 r;
    asm("mov.b64 {%0, %1}, %2;" : "=f"(r.x), "=f"(r.y) : "l"(v));
    return r;
}

// ---------------------------------------------------------------------------
// s[b,n] = r(n) * sum_nbr r(nbr) * x[b,nbr]
// ---------------------------------------------------------------------------
__global__ void k_init_s(const float* __restrict__ x, float* __restrict__ s) {
    int idx = blockIdx.x * 256 + threadIdx.x;
    if (idx >= NB * 2500) return;
    int b = idx / 2500, n = idx - b * 2500;
    int i = n / 50, j = n - i * 50;
    float acc = 0.f;
#pragma unroll
    for (int di = -1; di <= 1; di++)
#pragma unroll
        for (int dj = -1; dj <= 1; dj++) {
            int ii = i + di, jj = j + dj;
            if (ii >= 0 && ii < 50 && jj >= 0 && jj < 50)
                acc += rdeg(ii, jj, 50) * x[b * 2500 + ii * 50 + jj];
        }
    s[idx] = acc * rdeg(i, j, 50);
}

// ---------------------------------------------------------------------------
// p = w0 @ W11, q = b0 @ W11, plus the 9 channel-moment scalars with b11.
// ---------------------------------------------------------------------------
__global__ void k_prep(const float* __restrict__ w0, const float* __restrict__ b0,
                       const float* __restrict__ W11, const float* __restrict__ b11,
                       float* __restrict__ par) {
    __shared__ float ps[64], qs[64], bs[64];
    int d = threadIdx.x;
    float p = 0.f, q = 0.f;
    for (int c = 0; c < 64; c++) {
        float w = W11[c * 64 + d];
        p = fmaf(w0[c], w, p);
        q = fmaf(b0[c], w, q);
    }
    par[d] = p; par[64 + d] = q;
    ps[d] = p; qs[d] = q; bs[d] = b11[d];
    __syncthreads();
    if (d == 0) {
        float mp = 0, mq = 0, mb = 0, spp = 0, sqq = 0, sbb = 0, spq = 0, spb = 0, sqb = 0;
        for (int c = 0; c < 64; c++) {
            float pp = ps[c], qq = qs[c], bb = bs[c];
            mp += pp; mq += qq; mb += bb;
            spp = fmaf(pp, pp, spp); sqq = fmaf(qq, qq, sqq); sbb = fmaf(bb, bb, sbb);
            spq = fmaf(pp, qq, spq); spb = fmaf(pp, bb, spb); sqb = fmaf(qq, bb, sqb);
        }
        const float inv64 = 1.f / 64.f;
        par[128] = mp * inv64;  par[129] = mq * inv64;  par[130] = mb * inv64;
        par[131] = spp * inv64; par[132] = sqq * inv64; par[133] = sbb * inv64;
        par[134] = spq * inv64; par[135] = spb * inv64; par[136] = sqb * inv64;
    }
}

// ---------------------------------------------------------------------------
// x1[m,c] = celu( (alpha*p[c] + beta*q[c] + b11[c] - mean) * rsqrt(var+eps) )
// alpha = r(m)*T1, beta = r(m)*T2; T1 = sum_nbr r*s, T2 = sum_nbr r.
// grid (5,5,64), block 256; warp per node (2 channels / lane).
// ---------------------------------------------------------------------------
__global__ __launch_bounds__(256) void k_x1(const float* __restrict__ s,
                                            const float* __restrict__ par,
                                            const float* __restrict__ b11,
                                            float* __restrict__ out) {
    __shared__ float sh[12 * 12];
    __shared__ float ps[64], qs[64], bs[64], sc[9];
    const int tid = threadIdx.x;
    const int b = blockIdx.z;
    const int ti0 = blockIdx.y * 10, tj0 = blockIdx.x * 10;
    if (tid < 144) {
        int hi = tid / 12, hj = tid - hi * 12;
        int gi = ti0 - 1 + hi, gj = tj0 - 1 + hj;
        float v = 0.f;
        if (gi >= 0 && gi < 50 && gj >= 0 && gj < 50)
            v = s[b * 2500 + gi * 50 + gj];
        sh[tid] = v;
    }
    if (tid < 64) { ps[tid] = par[tid]; qs[tid] = par[64 + tid]; bs[tid] = b11[tid]; }
    else if (tid < 73) sc[tid - 64] = par[128 + tid - 64];
    __syncthreads();

    const int warp = tid >> 5, lane = tid & 31;
    for (int nd = warp; nd < 100; nd += 8) {
        int li = nd / 10, lj = nd - li * 10;
        int gi = ti0 + li, gj = tj0 + lj;
        float T1 = 0.f, T2 = 0.f;
#pragma unroll
        for (int di = 0; di < 3; di++)
#pragma unroll
            for (int dj = 0; dj < 3; dj++) {
                int ii = gi - 1 + di, jj = gj - 1 + dj;
                if (ii >= 0 && ii < 50 && jj >= 0 && jj < 50) {
                    float rr = rdeg(ii, jj, 50);
                    T1 = fmaf(rr, sh[(li + di) * 12 + (lj + dj)], T1);
                    T2 += rr;
                }
            }
        float r = rdeg(gi, gj, 50);
        float al = r * T1, be = r * T2;
        float mean = fmaf(al, sc[0], fmaf(be, sc[1], sc[2]));
        float e2 = al * al * sc[3] + be * be * sc[4] + sc[5]
                 + 2.f * (al * be * sc[6] + al * sc[7] + be * sc[8]);
        float inv = rsqrtf(e2 - mean * mean + 1e-5f);
        const int c0 = lane, c1 = lane + 32;
        float a0 = fmaf(al, ps[c0], fmaf(be, qs[c0], bs[c0]));
        float a1 = fmaf(al, ps[c1], fmaf(be, qs[c1], bs[c1]));
        float y0 = (a0 - mean) * inv;
        float y1 = (a1 - mean) * inv;
        y0 = y0 > 0.f ? y0 : expm1f(y0);
        y1 = y1 > 0.f ? y1 : expm1f(y1);
        float* op = out + ((size_t)b * 2500 + gi * 50 + gj) * 64;
        op[c0] = y0; op[c1] = y1;
    }
}

// ---------------------------------------------------------------------------
// GEMM (FFMA2): H[m,:] = r(m) * (X[m,:] @ W).  Tile 256 rows x 64 cols,
// 256 threads, thread = 8 rows x 8 cols (4 f32x2 accumulators per row).
// ---------------------------------------------------------------------------
template<int KSIDE>
__global__ __launch_bounds__(256) void k_gemm2(const float* __restrict__ X,
                                               const float* __restrict__ W,
                                               float* __restrict__ H, int M) {
    extern __shared__ float sg[];
    float* Xs = sg;                  // 256 * 65 (padded vs bank conflicts)
    float* Ws = sg + 256 * 65;       // 64 * 64
    const int tid = threadIdx.x;
    const int m0 = blockIdx.x * 256;

    for (int q = tid; q < 1024; q += 256)
        ((float4*)Ws)[q] = ((const float4*)W)[q];
    for (int q = tid; q < 4096; q += 256) {
        int row = q >> 4, part = q & 15;
        int gr = m0 + row;
        float4 v = make_float4(0.f, 0.f, 0.f, 0.f);
        if (gr < M) v = ((const float4*)(X + (size_t)gr * 64))[part];
        float* dst = Xs + row * 65 + part * 4;
        dst[0] = v.x; dst[1] = v.y; dst[2] = v.z; dst[3] = v.w;
    }
    __syncthreads();

    const int tx = tid & 7, ty = tid >> 3;
    const int r0 = ty * 8;
    unsigned long long acc[8][4];
#pragma unroll
    for (int i = 0; i < 8; i++)
#pragma unroll
        for (int j = 0; j < 4; j++) acc[i][j] = 0ULL;

#pragma unroll 2
    for (int k = 0; k < 64; k++) {
        const unsigned long long* wp =
            (const unsigned long long*)(Ws + k * 64 + (tx << 3));
        unsigned long long w0 = wp[0], w1 = wp[1], w2 = wp[2], w3 = wp[3];
#pragma unroll
        for (int i = 0; i < 8; i++) {
            unsigned long long aa = pk2(Xs[(r0 + i) * 65 + k]);
            fma2(acc[i][0], aa, w0);
            fma2(acc[i][1], aa, w1);
            fma2(acc[i][2], aa, w2);
            fma2(acc[i][3], aa, w3);
        }
    }

    constexpr int KK = KSIDE * KSIDE;
#pragma unroll
    for (int i = 0; i < 8; i++) {
        int gr = m0 + r0 + i;
        if (gr >= M) break;
        int n = gr % KK;
        int gi = n / KSIDE, gj = n - gi * KSIDE;
        float r = rdeg(gi, gj, KSIDE);
        float2 v0 = upk2(acc[i][0]), v1 = upk2(acc[i][1]);
        float2 v2 = upk2(acc[i][2]), v3 = upk2(acc[i][3]);
        float4* op = (float4*)(H + (size_t)gr * 64 + (tx << 3));
        op[0] = make_float4(v0.x * r, v0.y * r, v1.x * r, v1.y * r);
        op[1] = make_float4(v2.x * r, v2.y * r, v3.x * r, v3.y * r);
    }
}

// ---------------------------------------------------------------------------
// Stencil: y = celu(inorm(r(dst)*sum3x3(H) + bias) [+res]) [then 2x2 maxpool]
// RESM: 0 none, 1 full residual tensor, 2 rank-1 residual s*w0+b0.
// ---------------------------------------------------------------------------
template<int K, int TI, int TJ, bool POOL, int RESM>
__global__ __launch_bounds__(256) void k_stencil(const float* __restrict__ Hin,
                                                 const float* __restrict__ resid,
                                                 const float* __restrict__ w0,
                                                 const float* __restrict__ b0,
                                                 const float* __restrict__ bias,
                                                 float* __restrict__ out) {
    constexpr int HW = TJ + 2;
    constexpr int HN = (TI + 2) * (TJ + 2);
    constexpr int REG = POOL ? (K / 2) * 2 : K;

    extern __shared__ float sm[];
    float* Bs  = sm;             // 64
    float* W0s = sm + 64;        // 64
    float* B0s = sm + 128;       // 64
    float* Hs  = sm + 192;       // HN*64
    float* Ys  = Hs + HN * 64;   // TI*TJ*64 (POOL only)

    const int tid = threadIdx.x;
    const int b = blockIdx.z;
    const int ti0 = blockIdx.y * TI, tj0 = blockIdx.x * TJ;
    const size_t inB = (size_t)b * K * K * 64;

    if (tid < 16) ((float4*)Bs)[tid] = ((const float4*)bias)[tid];
    if (RESM == 2) {
        if (tid >= 16 && tid < 32)      ((float4*)W0s)[tid - 16] = ((const float4*)w0)[tid - 16];
        else if (tid >= 32 && tid < 48) ((float4*)B0s)[tid - 32] = ((const float4*)b0)[tid - 32];
    }
    for (int q = tid; q < HN * 16; q += 256) {
        int node = q >> 4, part = q & 15;
        int hi = node / HW, hj = node - hi * HW;
        int gi = ti0 - 1 + hi, gj = tj0 - 1 + hj;
        float4 v = make_float4(0.f, 0.f, 0.f, 0.f);
        if (gi >= 0 && gi < K && gj >= 0 && gj < K)
            v = ((const float4*)(Hin + inB + (size_t)(gi * K + gj) * 64))[part];
        ((float4*)(Hs + node * 64))[part] = v;
    }
    __syncthreads();

    const int warp = tid >> 5, lane = tid & 31;
    for (int nd = warp; nd < TI * TJ; nd += 8) {
        int li = nd / TJ, lj = nd - li * TJ;
        int gi = ti0 + li, gj = tj0 + lj;
        if (gi >= REG || gj >= REG) continue;
        const int c0 = lane, c1 = lane + 32;
        float a0 = 0.f, a1 = 0.f;
#pragma unroll
        for (int di = 0; di < 3; di++)
#pragma unroll
            for (int dj = 0; dj < 3; dj++) {
                const float* h = Hs + ((li + di) * HW + (lj + dj)) * 64;
                a0 += h[c0]; a1 += h[c1];
            }
        float r = rdeg(gi, gj, K);
        a0 = fmaf(a0, r, Bs[c0]);
        a1 = fmaf(a1, r, Bs[c1]);
        float sv = a0 + a1, sq = a0 * a0 + a1 * a1;
#pragma unroll
        for (int o = 16; o; o >>= 1) {
            sv += __shfl_xor_sync(0xffffffffu, sv, o);
            sq += __shfl_xor_sync(0xffffffffu, sq, o);
        }
        float mean = sv * (1.f / 64.f);
        float var  = sq * (1.f / 64.f) - mean * mean;
        float inv  = rsqrtf(var + 1e-5f);
        float y0 = (a0 - mean) * inv;
        float y1 = (a1 - mean) * inv;
        if (RESM == 1) {
            const float* rp = resid + inB + (size_t)(gi * K + gj) * 64;
            y0 += rp[c0]; y1 += rp[c1];
        } else if (RESM == 2) {
            float sval = resid[(size_t)b * K * K + gi * K + gj];
            y0 = fmaf(sval, W0s[c0], y0 + B0s[c0]);
            y1 = fmaf(sval, W0s[c1], y1 + B0s[c1]);
        }
        y0 = y0 > 0.f ? y0 : expm1f(y0);
        y1 = y1 > 0.f ? y1 : expm1f(y1);
        if (!POOL) {
            float* op = out + inB + (size_t)(gi * K + gj) * 64;
            op[c0] = y0; op[c1] = y1;
        } else {
            float* yp = Ys + nd * 64;
            yp[c0] = y0; yp[c1] = y1;
        }
    }

    if (POOL) {
        __syncthreads();
        constexpr int KP = K / 2;
        constexpr int PT = (TI / 2) * (TJ / 2);
        const size_t outB = (size_t)b * KP * KP * 64;
        for (int q = tid; q < PT * 64; q += 256) {
            int pn = q >> 6, c = q & 63;
            int pi = pn / (TJ / 2), pj = pn - pi * (TJ / 2);
            int li = pi * 2, lj = pj * 2;
            float m0 = fmaxf(Ys[(li * TJ + lj) * 64 + c],
                             Ys[(li * TJ + lj + 1) * 64 + c]);
            float m1 = fmaxf(Ys[((li + 1) * TJ + lj) * 64 + c],
                             Ys[((li + 1) * TJ + lj + 1) * 64 + c]);
            int gpi = ti0 / 2 + pi, gpj = tj0 / 2 + pj;
            out[outB + (size_t)(gpi * KP + gpj) * 64 + c] = fmaxf(m0, m1);
        }
    }
}

// ---------------------------------------------------------------------------
// G += W[i0:,k0:] @ W[j0:,k0:]^T  (split-K, atomic)
// ---------------------------------------------------------------------------
__global__ __launch_bounds__(256) void k_gram(const float* __restrict__ W, int Nf,
                                              float* __restrict__ G) {
    extern __shared__ float sh[];
    float* As = sh;              // 64*130
    float* Bsm = sh + 64 * 130;  // 64*130
    const int tid = threadIdx.x;
    const int j0 = blockIdx.x * 64, i0 = blockIdx.y * 64, k0 = blockIdx.z * 128;
    for (int q = tid; q < 2048; q += 256) {
        int r = q >> 5, c = (q & 31) * 4;
        float4 v = *(const float4*)(W + (size_t)(i0 + r) * Nf + k0 + c);
        As[r * 130 + c] = v.x; As[r * 130 + c + 1] = v.y;
        As[r * 130 + c + 2] = v.z; As[r * 130 + c + 3] = v.w;
        float4 u = *(const float4*)(W + (size_t)(j0 + r) * Nf + k0 + c);
        Bsm[r * 130 + c] = u.x; Bsm[r * 130 + c + 1] = u.y;
        Bsm[r * 130 + c + 2] = u.z; Bsm[r * 130 + c + 3] = u.w;
    }
    __syncthreads();
    const int tx = tid & 15, ty = tid >> 4;
    float acc[4][4];
#pragma unroll
    for (int i = 0; i < 4; i++)
        acc[i][0] = acc[i][1] = acc[i][2] = acc[i][3] = 0.f;
#pragma unroll 4
    for (int k = 0; k < 128; k += 2) {
        float2 a[4], bb[4];
#pragma unroll
        for (int i = 0; i < 4; i++) a[i]  = *(const float2*)(As  + (ty * 4 + i) * 130 + k);
#pragma unroll
        for (int j = 0; j < 4; j++) bb[j] = *(const float2*)(Bsm + (tx * 4 + j) * 130 + k);
#pragma unroll
        for (int i = 0; i < 4; i++)
#pragma unroll
            for (int j = 0; j < 4; j++)
                acc[i][j] = fmaf(a[i].y, bb[j].y, fmaf(a[i].x, bb[j].x, acc[i][j]));
    }
#pragma unroll
    for (int i = 0; i < 4; i++)
#pragma unroll
        for (int j = 0; j < 4; j++)
            atomicAdd(&G[(size_t)(i0 + ty * 4 + i) * 256 + j0 + tx * 4 + j], acc[i][j]);
}

__device__ __forceinline__ float blockReduce1024(float x, float* red) {
#pragma unroll
    for (int o = 16; o; o >>= 1) x += __shfl_xor_sync(0xffffffffu, x, o);
    if ((threadIdx.x & 31) == 0) red[threadIdx.x >> 5] = x;
    __syncthreads();
    float tot = 0.f;
#pragma unroll
    for (int i = 0; i < 32; i++) tot += red[i];
    __syncthreads();
    return tot;
}

// ---------------------------------------------------------------------------
// Power iteration, 1024 threads: 29x u <- normalize(G u), 30th matvec gives
// z = G u_29. sigma from |Wv| = |G u_29| / (|W^T u_29| + 1e-12) -- the
// expensive uncoalesced Wv pass is algebraically eliminated.
// ---------------------------------------------------------------------------
__global__ __launch_bounds__(1024) void k_power(const float* __restrict__ lw1,
                                                const float* __restrict__ lw2,
                                                const float* __restrict__ G1,
                                                const float* __restrict__ G2,
                                                float* __restrict__ sig) {
    const float* G  = blockIdx.x == 0 ? G1 : G2;
    const float* W  = blockIdx.x == 0 ? lw1 : lw2;
    const int   Nf  = blockIdx.x == 0 ? 2304 : 256;
    __shared__ float u[256];
    __shared__ float part[4][256];
    __shared__ float red[32];
    const int tid = threadIdx.x;
    const int row = tid & 255, seg = tid >> 8;
    if (tid < 256) u[tid] = 1.f / 16.f;
    __syncthreads();
    float nz2 = 0.f;
    for (int it = 0; it < 30; it++) {
        const float* gp = G + (size_t)(seg * 64) * 256 + row;
        const float* up = u + seg * 64;
        float a0 = 0.f, a1 = 0.f, a2 = 0.f, a3 = 0.f;
#pragma unroll 4
        for (int j = 0; j < 64; j += 4) {
            a0 = fmaf(gp[(j + 0) * 256], up[j + 0], a0);
            a1 = fmaf(gp[(j + 1) * 256], up[j + 1], a1);
            a2 = fmaf(gp[(j + 2) * 256], up[j + 2], a2);
            a3 = fmaf(gp[(j + 3) * 256], up[j + 3], a3);
        }
        part[seg][row] = (a0 + a1) + (a2 + a3);
        __syncthreads();
        float tot = 0.f;
        if (tid < 256)
            tot = part[0][tid] + part[1][tid] + part[2][tid] + part[3][tid];
        float n2 = blockReduce1024(tot * tot, red);
        if (it == 29) nz2 = n2;
        else if (tid < 256) u[tid] = tot / (sqrtf(n2) + 1e-12f);
        __syncthreads();
    }
    // nv2 = |W^T u_29|^2  (coalesced over columns)
    float ss = 0.f;
    for (int j = tid; j < Nf; j += 1024) {
        float acc = 0.f;
#pragma unroll 8
        for (int i = 0; i < 256; i++)
            acc = fmaf(W[(size_t)i * Nf + j], u[i], acc);
        ss += acc * acc;
    }
    float nv2 = blockReduce1024(ss, red);
    if (tid == 0) {
        float t = sqrtf(nz2) / (sqrtf(nv2) + 1e-12f);   // |W v_30|
        sig[blockIdx.x] = t * t / (t + 1e-12f);
    }
}

// ---------------------------------------------------------------------------
// h1 = celu(F @ W1^T / sigma1 + b1)   F:[64,2304], W1:[256,2304]
// ---------------------------------------------------------------------------
__global__ void k_lin1(const float* __restrict__ F, const float* __restrict__ W,
                       const float* __restrict__ bias, const float* __restrict__ sig,
                       float* __restrict__ out) {
    __shared__ float Fs[4 * 2304];
    __shared__ float part[4][4][64];
    const int tid = threadIdx.x;
    const int og = blockIdx.x, bg = blockIdx.y;
    const float4* src = (const float4*)(F + (size_t)bg * 4 * 2304);
    for (int q = tid; q < 2304; q += 256) ((float4*)Fs)[q] = src[q];
    __syncthreads();
    const int ol = tid & 63, ks = tid >> 6;
    const int o = og * 64 + ol;
    const float* wr = W + (size_t)o * 2304 + ks * 576;
    const float* fb = Fs + ks * 576;
    float a0 = 0.f, a1 = 0.f, a2 = 0.f, a3 = 0.f;
#pragma unroll 4
    for (int k = 0; k < 576; k++) {
        float w = wr[k];
        a0 = fmaf(w, fb[k],        a0);
        a1 = fmaf(w, fb[2304 + k], a1);
        a2 = fmaf(w, fb[4608 + k], a2);
        a3 = fmaf(w, fb[6912 + k], a3);
    }
    part[ks][0][ol] = a0; part[ks][1][ol] = a1;
    part[ks][2][ol] = a2; part[ks][3][ol] = a3;
    __syncthreads();
    if (ks == 0) {
        float s0 = sig[0], bo = bias[o];
#pragma unroll
        for (int bb = 0; bb < 4; bb++) {
            float z = part[0][bb][ol] + part[1][bb][ol] + part[2][bb][ol] + part[3][bb][ol];
            z = z / s0 + bo;
            out[(size_t)(bg * 4 + bb) * 256 + o] = z > 0.f ? z : expm1f(z);
        }
    }
}

__global__ void k_lin2(const float* __restrict__ h1, const float* __restrict__ W,
                       const float* __restrict__ bias, const float* __restrict__ sig,
                       float* __restrict__ out) {
    const int b = blockIdx.x, o = threadIdx.x;
    __shared__ float hs[256];
    hs[o] = h1[b * 256 + o];
    __syncthreads();
    const float* wr = W + o * 256;
    float acc = 0.f;
#pragma unroll 8
    for (int k = 0; k < 256; k++) acc = fmaf(wr[k], hs[k], acc);
    acc = acc / sig[1] + bias[o];
    out[b * 256 + o] = acc > 0.f ? acc : expm1f(acc);
}

// ---------------------------------------------------------------------------
extern "C" void kernel_launch(void* const* d_in, const int* in_sizes, int n_in,
                              void* d_out, int out_size) {
    const float* x      = (const float*)d_in[0];
    const float* w_init = (const float*)d_in[1];
    const float* b_init = (const float*)d_in[2];
    const float* w11 = (const float*)d_in[3];  const float* b11 = (const float*)d_in[4];
    const float* w12 = (const float*)d_in[5];  const float* b12 = (const float*)d_in[6];
    const float* w21 = (const float*)d_in[7];  const float* b21 = (const float*)d_in[8];
    const float* w22 = (const float*)d_in[9];  const float* b22 = (const float*)d_in[10];
    const float* w31 = (const float*)d_in[11]; const float* b31 = (const float*)d_in[12];
    const float* w32 = (const float*)d_in[13]; const float* b32 = (const float*)d_in[14];
    const float* lw1 = (const float*)d_in[15]; const float* lb1 = (const float*)d_in[16];
    const float* lw2 = (const float*)d_in[17]; const float* lb2 = (const float*)d_in[18];

    float *pS, *pX1, *pH, *pP1, *pP2, *pF, *pG1, *pG2, *pSig, *pH1, *pPar;
    cudaGetSymbolAddress((void**)&pS,  g_s);
    cudaGetSymbolAddress((void**)&pX1, g_X1);
    cudaGetSymbolAddress((void**)&pH,  g_H);
    cudaGetSymbolAddress((void**)&pP1, g_P1);
    cudaGetSymbolAddress((void**)&pP2, g_P2);
    cudaGetSymbolAddress((void**)&pF,  g_F);
    cudaGetSymbolAddress((void**)&pG1, g_G1);
    cudaGetSymbolAddress((void**)&pG2, g_G2);
    cudaGetSymbolAddress((void**)&pSig, g_Sig);
    cudaGetSymbolAddress((void**)&pH1, g_H1);
    cudaGetSymbolAddress((void**)&pPar, g_Par);

    const size_t sg2 = (256 * 65 + 64 * 64) * sizeof(float);              // 82944
    const size_t sgr = 2 * 64 * 130 * sizeof(float);                      // 66560
    const size_t s1b = (192 + 144 * 64 + 100 * 64) * sizeof(float);       // 63232
    const size_t s2a = (192 + 121 * 64) * sizeof(float);                  // 31744
    const size_t s2b = (192 + 100 * 64 + 64 * 64) * sizeof(float);        // 42752
    const size_t s3a = (192 +  64 * 64) * sizeof(float);                  // 17152
    const size_t s3b = (192 +  64 * 64 + 36 * 64) * sizeof(float);        // 26368

    cudaFuncSetAttribute(k_gemm2<50>, cudaFuncAttributeMaxDynamicSharedMemorySize, (int)sg2);
    cudaFuncSetAttribute(k_gemm2<25>, cudaFuncAttributeMaxDynamicSharedMemorySize, (int)sg2);
    cudaFuncSetAttribute(k_gemm2<12>, cudaFuncAttributeMaxDynamicSharedMemorySize, (int)sg2);
    cudaFuncSetAttribute(k_gram,      cudaFuncAttributeMaxDynamicSharedMemorySize, (int)sgr);
    cudaFuncSetAttribute(k_stencil<50,10,10,true, 2>, cudaFuncAttributeMaxDynamicSharedMemorySize, (int)s1b);
    cudaFuncSetAttribute(k_stencil<25, 9, 9,false,0>, cudaFuncAttributeMaxDynamicSharedMemorySize, (int)s2a);
    cudaFuncSetAttribute(k_stencil<25, 8, 8,true, 1>, cudaFuncAttributeMaxDynamicSharedMemorySize, (int)s2b);
    cudaFuncSetAttribute(k_stencil<12, 6, 6,false,0>, cudaFuncAttributeMaxDynamicSharedMemorySize, (int)s3a);
    cudaFuncSetAttribute(k_stencil<12, 6, 6,true, 1>, cudaFuncAttributeMaxDynamicSharedMemorySize, (int)s3b);

    const int M1 = NB * 2500, M2 = NB * 625, M3 = NB * 144;

    // stage 1 (k=50): rank-1 first GCN
    k_init_s<<<(M1 + 255) / 256, 256>>>(x, pS);
    k_prep<<<1, 64>>>(w_init, b_init, w11, b11, pPar);
    k_x1<<<dim3(5, 5, NB), 256>>>(pS, pPar, b11, pX1);
    k_gemm2<50><<<(M1 + 255) / 256, 256, sg2>>>(pX1, w12, pH, M1);
    k_stencil<50,10,10,true, 2><<<dim3(5,5,NB), 256, s1b>>>(pH, pS, w_init, b_init, b12, pP1);
    // stage 2 (k=25)
    k_gemm2<25><<<(M2 + 255) / 256, 256, sg2>>>(pP1, w21, pH, M2);
    k_stencil<25, 9, 9,false,0><<<dim3(3,3,NB), 256, s2a>>>(pH, nullptr, nullptr, nullptr, b21, pX1);
    k_gemm2<25><<<(M2 + 255) / 256, 256, sg2>>>(pX1, w22, pH, M2);
    k_stencil<25, 8, 8,true, 1><<<dim3(3,3,NB), 256, s2b>>>(pH, pP1, nullptr, nullptr, b22, pP2);
    // stage 3 (k=12)
    k_gemm2<12><<<(M3 + 255) / 256, 256, sg2>>>(pP2, w31, pH, M3);
    k_stencil<12, 6, 6,false,0><<<dim3(2,2,NB), 256, s3a>>>(pH, nullptr, nullptr, nullptr, b31, pX1);
    k_gemm2<12><<<(M3 + 255) / 256, 256, sg2>>>(pX1, w32, pH, M3);
    k_stencil<12, 6, 6,true, 1><<<dim3(2,2,NB), 256, s3b>>>(pH, pP2, nullptr, nullptr, b32, pF);

    // spectral-norm head
    cudaMemsetAsync(pG1, 0, 256 * 256 * sizeof(float));
    cudaMemsetAsync(pG2, 0, 256 * 256 * sizeof(float));
    k_gram<<<dim3(4,4,18), 256, sgr>>>(lw1, 2304, pG1);
    k_gram<<<dim3(4,4, 2), 256, sgr>>>(lw2,  256, pG2);
    k_power<<<2, 1024>>>(lw1, lw2, pG1, pG2, pSig);
    k_lin1<<<dim3(4,16), 256>>>(pF, lw1, lb1, pSig, pH1);
    k_lin2<<<64, 256>>>(pH1, lw2, lb2, pSig, (float*)d_out);
}